// round 9
// baseline (speedup 1.0000x reference)
#include <cuda_runtime.h>

// InteractionArch: out[b] = concat(dense[b] (128), sparse[b]·dense[b] (26),
//                                  triu_{k=1}(sparse[b]·sparse[b]^T) (325))
// B=16384, F=26, D=128, out stride 479 fp32 (row base only 4B-aligned).
//
// R9: k-major smem tile Xs[k][28] -> warp-broadcast LDS. At fixed k one
// LDS.128 serves all lanes' 4 tile vectors (7 distinct addrs, distinct bank
// quads) = 1 crossbar phase. 2 LDS/k vs 8 phases/k in R7 (4x less crossbar).
// Transpose done at fill: per-lane LDG.128 stream + conflict-free scalar STS.
// FFMA2 packed over jj (xj pair direct from LDS; xi dup via mov.b64).

#define B_TOT 16384
#define NF 26
#define DD 128
#define NV 28           // 26 sparse + dense(26) + zero(27)
#define CHUNK 32        // k's per chunk
#define NCH 4
#define OUT_STRIDE 479

__device__ __forceinline__ unsigned long long dup2(float x) {
    unsigned long long r;
    asm("mov.b64 %0, {%1, %1};" : "=l"(r) : "f"(x));
    return r;
}
// packed f32x2 fma: acc(2xf32) += a(2xf32) * b(2xf32)
__device__ __forceinline__ void ffma2(unsigned long long& acc,
                                      unsigned long long a,
                                      unsigned long long b) {
    asm("fma.rn.f32x2 %0, %1, %2, %0;" : "+l"(acc) : "l"(a), "l"(b));
}

__global__ void __launch_bounds__(32, 24) interact_kernel(
    const float* __restrict__ dense,
    const float* __restrict__ sparse,
    float* __restrict__ out)
{
    __shared__ float Xs[CHUNK][NV];   // 3584 B, k-major

    const int lane = threadIdx.x;
    const int b    = blockIdx.x;

    // ---- dense passthrough to out[0:128] (scalar stores; base only 4B-aligned) ----
    {
        float4 dv = reinterpret_cast<const float4*>(dense + (size_t)b * DD)[lane];
        float* ob = out + (size_t)b * OUT_STRIDE;
        ob[4 * lane + 0] = dv.x;
        ob[4 * lane + 1] = dv.y;
        ob[4 * lane + 2] = dv.z;
        ob[4 * lane + 3] = dv.w;
    }

    // lane v owns vector v: 0..25 sparse, 26 dense, 27 zero, 28-31 idle
    const float* __restrict__ src =
        (lane < NF) ? sparse + (size_t)b * NF * DD + (size_t)lane * DD
                    : dense + (size_t)b * DD;           // lane 26 (27+ unused)

    float4 g[8];   // staged chunk of own vector

    auto load_g = [&](int c) {
        if (lane < 27) {
            #pragma unroll
            for (int q = 0; q < 8; q++)
                g[q] = *reinterpret_cast<const float4*>(src + c * CHUNK + q * 4);
        } else {
            #pragma unroll
            for (int q = 0; q < 8; q++)
                g[q] = make_float4(0.f, 0.f, 0.f, 0.f);
        }
    };
    auto sts_g = [&]() {
        if (lane < NV) {
            #pragma unroll
            for (int q = 0; q < 8; q++) {
                Xs[q * 4 + 0][lane] = g[q].x;   // 1 phase: 28 distinct banks
                Xs[q * 4 + 1][lane] = g[q].y;
                Xs[q * 4 + 2][lane] = g[q].z;
                Xs[q * 4 + 3][lane] = g[q].w;
            }
        }
    };

    // ---- lane -> 4x4 tile of the 7x7 tile grid (28 upper-tri tiles) ----
    int ti = 0, rem = (lane < 28) ? lane : 0;
    #pragma unroll
    for (int s = 0; s < 6; s++)
        if (rem >= 7 - ti) { rem -= 7 - ti; ti++; }
    const int tj = ti + rem;
    const bool active = (lane < 28);

    unsigned long long acc2[4][2];   // acc2[ii][p]: (acc[ii][2p], acc[ii][2p+1])
    #pragma unroll
    for (int ii = 0; ii < 4; ii++) { acc2[ii][0] = 0ULL; acc2[ii][1] = 0ULL; }

    const float* __restrict__ base = &Xs[0][0];

    // ---- chunk loop: LDG prefetch overlaps compute; single buffer + syncwarp ----
    load_g(0);
    #pragma unroll
    for (int c = 0; c < NCH; c++) {
        __syncwarp();            // all lanes done reading Xs (prev chunk)
        sts_g();
        __syncwarp();            // stores visible warp-wide
        if (c + 1 < NCH) load_g(c + 1);   // in flight during compute

        #pragma unroll 4
        for (int k = 0; k < CHUNK; k++) {
            const float*      rk  = base + k * NV;
            float4            xi4 = *reinterpret_cast<const float4*>(rk + 4 * ti);
            ulonglong2        xjp = *reinterpret_cast<const ulonglong2*>(rk + 4 * tj);
            unsigned long long d0 = dup2(xi4.x), d1 = dup2(xi4.y),
                               d2 = dup2(xi4.z), d3 = dup2(xi4.w);
            ffma2(acc2[0][0], d0, xjp.x);  ffma2(acc2[0][1], d0, xjp.y);
            ffma2(acc2[1][0], d1, xjp.x);  ffma2(acc2[1][1], d1, xjp.y);
            ffma2(acc2[2][0], d2, xjp.x);  ffma2(acc2[2][1], d2, xjp.y);
            ffma2(acc2[3][0], d3, xjp.x);  ffma2(acc2[3][1], d3, xjp.y);
        }
    }

    // ---- epilogue: unpack pairs + scatter needed dots (i<j, j<=26) ----
    if (!active) return;
    float* ob = out + (size_t)b * OUT_STRIDE;
    #pragma unroll
    for (int ii = 0; ii < 4; ii++) {
        #pragma unroll
        for (int p = 0; p < 2; p++) {
            float2 pr = *reinterpret_cast<float2*>(&acc2[ii][p]);
            #pragma unroll
            for (int h = 0; h < 2; h++) {
                const int i = 4 * ti + ii;
                const int j = 4 * tj + 2 * p + h;
                const float v = h ? pr.y : pr.x;
                if (i < j && j <= 26) {
                    int dst;
                    if (j == 26) {
                        dst = 128 + i;                                        // sparse·dense
                    } else {
                        dst = 154 + i * 25 - (i * (i - 1)) / 2 + (j - i - 1); // pair
                    }
                    ob[dst] = v;
                }
            }
        }
    }
}

extern "C" void kernel_launch(void* const* d_in, const int* in_sizes, int n_in,
                              void* d_out, int out_size)
{
    (void)n_in; (void)out_size;
    const float* a = (const float*)d_in[0];
    const float* b = (const float*)d_in[1];
    // dense has B*D = 2,097,152 elems; sparse has B*F*D = 54,525,952 elems.
    const float* dense  = (in_sizes[0] < in_sizes[1]) ? a : b;
    const float* sparse = (in_sizes[0] < in_sizes[1]) ? b : a;

    interact_kernel<<<B_TOT, 32>>>(dense, sparse, (float*)d_out);
}

// round 11
// speedup vs baseline: 1.2370x; 1.2370x over previous
#include <cuda_runtime.h>

// InteractionArch: out[b] = concat(dense[b] (128), sparse[b]·dense[b] (26),
//                                  triu_{k=1}(sparse[b]·sparse[b]^T) (325))
// B=16384, F=26, D=128, out stride 479 fp32 (row base only 4B-aligned).
//
// R11: 7x7 register tiles (4x4 tile grid over 28 vectors, 10 upper-tri
// tiles), 1 lane/tile, 3 batch rows/warp (30 active lanes). Double-buffered
// cp.async 16-float k-chunks; 20-float padded rows make all LDS.128 phases
// conflict-free (bank group 5v mod 8) with broadcast reuse. jj-inner operand
// scheduling keeps regs ~110 -> __launch_bounds__(32,16): 16 warps/SM.

#define B_TOT 16384
#define NF 26
#define DD 128
#define NV 28
#define CHUNK 16          // floats per k-chunk
#define CQ 4              // float4 quads per chunk
#define NCH 8             // chunks (128/16)
#define RSTRIDE 20        // padded floats per vector row (80 B, 16B-aligned)
#define OUT_STRIDE 479
#define RPW 3             // batch rows per warp

__device__ __forceinline__ void cp_async16(void* smem, const void* gmem) {
    unsigned s = (unsigned)__cvta_generic_to_shared(smem);
    asm volatile("cp.async.cg.shared.global [%0], [%1], 16;" :: "r"(s), "l"(gmem));
}
__device__ __forceinline__ void cp_commit() {
    asm volatile("cp.async.commit_group;");
}
template <int N>
__device__ __forceinline__ void cp_wait() {
    asm volatile("cp.async.wait_group %0;" :: "n"(N));
}

__global__ void __launch_bounds__(32, 16) interact_kernel(
    const float* __restrict__ dense,
    const float* __restrict__ sparse,
    float* __restrict__ out)
{
    __shared__ float Xs[RPW][2][NV][RSTRIDE];   // 13440 B

    const int lane = threadIdx.x;
    const int b0   = blockIdx.x * RPW;

    // ---- zero pad slot 27 (both buffers, first 16 floats; never overwritten) ----
    #pragma unroll
    for (int t = 0; t < 3; t++) {
        int idx = lane + 32 * t;               // RPW*2*CHUNK = 96 floats
        int rr  = idx / (2 * CHUNK);
        int rem = idx - rr * 2 * CHUNK;
        Xs[rr][rem / CHUNK][27][rem % CHUNK] = 0.f;
    }

    // ---- dense passthrough to out[0:128] (scalar stores; base only 4B-aligned) ----
    #pragma unroll
    for (int r = 0; r < RPW; r++) {
        const int b = b0 + r;
        if (b >= B_TOT) break;
        float4 dv = reinterpret_cast<const float4*>(dense + (size_t)b * DD)[lane];
        float* ob = out + (size_t)b * OUT_STRIDE;
        ob[4 * lane + 0] = dv.x;
        ob[4 * lane + 1] = dv.y;
        ob[4 * lane + 2] = dv.z;
        ob[4 * lane + 3] = dv.w;
    }

    // ---- chunk loader (warp-cooperative): 26*4 sparse + 4 dense quads x 3 rows ----
    auto load_chunk = [&](int c, int buf) {
        #pragma unroll
        for (int t = 0; t < 10; t++) {
            int idx = lane + 32 * t;
            if (idx < NF * CQ * RPW) {
                int r   = idx / (NF * CQ);
                int rem = idx - r * NF * CQ;
                int v   = rem >> 2;
                int q   = rem & 3;
                int b   = b0 + r;
                if (b < B_TOT) {
                    const float* g = sparse + (size_t)b * NF * DD + v * DD + c * CHUNK + q * 4;
                    cp_async16(&Xs[r][buf][v][q * 4], g);
                }
            }
        }
        if (lane < CQ * RPW) {
            int r = lane >> 2, q = lane & 3;
            int b = b0 + r;
            if (b < B_TOT)
                cp_async16(&Xs[r][buf][26][q * 4],
                           dense + (size_t)b * DD + c * CHUNK + q * 4);
        }
        cp_commit();
    };

    // ---- lane -> (row, tile): 3 rows x 10 upper-tri tiles of the 4x4 grid ----
    const int r  = lane / 10;                  // 0..2 (lanes 30,31 idle in compute)
    const int t  = lane - r * 10;              // 0..9
    const int bc = b0 + r;
    const bool active = (lane < 30) && (bc < B_TOT);

    const int ti = (t < 4) ? 0 : (t < 7) ? 1 : (t < 9) ? 2 : 3;
    const int tj = (t < 4) ? t : (t < 7) ? t - 3 : (t < 9) ? t - 5 : 3;
    const bool diag = (ti == tj);

    float acc[7][7];
    #pragma unroll
    for (int ii = 0; ii < 7; ii++)
        #pragma unroll
        for (int jj = 0; jj < 7; jj++)
            acc[ii][jj] = 0.f;

    // ---- pipelined chunk loop ----
    load_chunk(0, 0);
    #pragma unroll 1
    for (int c = 0; c < NCH; c++) {
        const int buf = c & 1;
        if (c + 1 < NCH) { load_chunk(c + 1, buf ^ 1); cp_wait<1>(); }
        else             { cp_wait<0>(); }
        __syncwarp();

        if (active) {
            const float* __restrict__ pi = &Xs[r][buf][7 * ti][0];
            const float* __restrict__ pj = &Xs[r][buf][7 * tj][0];
            #pragma unroll
            for (int kk = 0; kk < CQ; kk++) {
                float4 xi[7];
                #pragma unroll
                for (int ii = 0; ii < 7; ii++)
                    xi[ii] = *reinterpret_cast<const float4*>(pi + ii * RSTRIDE + kk * 4);
                #pragma unroll
                for (int jj = 0; jj < 7; jj++) {
                    float4 xj = diag ? xi[jj]
                              : *reinterpret_cast<const float4*>(pj + jj * RSTRIDE + kk * 4);
                    #pragma unroll
                    for (int ii = 0; ii < 7; ii++) {
                        float s = acc[ii][jj];
                        s = fmaf(xi[ii].x, xj.x, s);
                        s = fmaf(xi[ii].y, xj.y, s);
                        s = fmaf(xi[ii].z, xj.z, s);
                        s = fmaf(xi[ii].w, xj.w, s);
                        acc[ii][jj] = s;
                    }
                }
            }
        }
        __syncwarp();   // all lanes done reading buf before it is refilled
    }

    // ---- epilogue: scatter needed dots (i<j, j<=26) ----
    if (!active) return;
    float* ob = out + (size_t)bc * OUT_STRIDE;
    #pragma unroll
    for (int ii = 0; ii < 7; ii++) {
        #pragma unroll
        for (int jj = 0; jj < 7; jj++) {
            const int i = 7 * ti + ii;
            const int j = 7 * tj + jj;
            if (i < j && j <= 26) {
                int dst;
                if (j == 26) {
                    dst = 128 + i;                                        // sparse·dense
                } else {
                    dst = 154 + i * 25 - (i * (i - 1)) / 2 + (j - i - 1); // pair
                }
                ob[dst] = acc[ii][jj];
            }
        }
    }
}

extern "C" void kernel_launch(void* const* d_in, const int* in_sizes, int n_in,
                              void* d_out, int out_size)
{
    (void)n_in; (void)out_size;
    const float* a = (const float*)d_in[0];
    const float* b = (const float*)d_in[1];
    // dense has B*D = 2,097,152 elems; sparse has B*F*D = 54,525,952 elems.
    const float* dense  = (in_sizes[0] < in_sizes[1]) ? a : b;
    const float* sparse = (in_sizes[0] < in_sizes[1]) ? b : a;

    const int grid = (B_TOT + RPW - 1) / RPW;
    interact_kernel<<<grid, 32>>>(dense, sparse, (float*)d_out);
}

// round 12
// speedup vs baseline: 1.6941x; 1.3695x over previous
#include <cuda_runtime.h>
#include <cstdint>

// InteractionArch: out[b] = concat(dense[b] (128), sparse[b]·dense[b] (26),
//                                  triu_{k=1}(sparse[b]·sparse[b]^T) (325))
// B=16384, F=26, D=128, out stride 479 fp32 (row base only 4B-aligned).
//
// R12: bulk-DMA fill. Per block (1 warp), 3 batch rows staged whole via
// cp.async.bulk (sparse block is 13312B contiguous; dense 512B) completed by
// one mbarrier -> zero per-lane fill instructions. Compute: 7x7 register
// tiles (10 upper-tri tiles of the 4x4 grid over 28 vectors), 1 lane/tile,
// 3 rows/warp (30 lanes), conflict-free rotated LDS.128, packed fma.rn.f32x2.
// 43KB smem -> 5 blocks/SM; crossbar floor 149 LDS-inst/row.

#define B_TOT 16384
#define NF 26
#define DD 128
#define NV 28
#define NQ 32            // float4 quads per vector
#define OUT_STRIDE 479
#define RPW 3
#define SP_BYTES (NF * DD * 4)   // 13312
#define DN_BYTES (DD * 4)        // 512

__device__ __forceinline__ uint32_t smem_u32(const void* p) {
    uint32_t a;
    asm("{ .reg .u64 t; cvta.to.shared.u64 t, %1; cvt.u32.u64 %0, t; }" : "=r"(a) : "l"(p));
    return a;
}
__device__ __forceinline__ void bulk_ld(uint32_t dst, const void* src,
                                        uint32_t bytes, uint32_t mbar) {
    asm volatile(
        "cp.async.bulk.shared::cta.global.mbarrier::complete_tx::bytes "
        "[%0], [%1], %2, [%3];"
        :: "r"(dst), "l"(src), "r"(bytes), "r"(mbar) : "memory");
}
// packed f32x2 fma: acc(2xf32) += a(2xf32) * b(2xf32)
__device__ __forceinline__ void ffma2(unsigned long long& acc,
                                      unsigned long long a,
                                      unsigned long long b) {
    asm("fma.rn.f32x2 %0, %1, %2, %0;" : "+l"(acc) : "l"(a), "l"(b));
}

__global__ void __launch_bounds__(32) interact_kernel(
    const float* __restrict__ dense,
    const float* __restrict__ sparse,
    float* __restrict__ out)
{
    __shared__ float Xs[RPW][NV][DD];                  // 43008 B
    __shared__ __align__(8) unsigned long long mbar_s;

    const int lane = threadIdx.x;
    const int b0   = blockIdx.x * RPW;
    const uint32_t mbar = smem_u32(&mbar_s);

    // ---- init mbarrier, then issue bulk loads (thread 0) ----
    if (lane == 0) {
        asm volatile("mbarrier.init.shared.b64 [%0], %1;" :: "r"(mbar), "r"(1u) : "memory");
    }
    __syncwarp();
    if (lane == 0) {
        int nvalid = 0;
        #pragma unroll
        for (int r = 0; r < RPW; r++)
            if (b0 + r < B_TOT) nvalid++;
        const uint32_t tx = (uint32_t)nvalid * (SP_BYTES + DN_BYTES);
        asm volatile("mbarrier.arrive.expect_tx.shared.b64 _, [%0], %1;"
                     :: "r"(mbar), "r"(tx) : "memory");
        #pragma unroll
        for (int r = 0; r < RPW; r++) {
            const int b = b0 + r;
            if (b < B_TOT) {
                bulk_ld(smem_u32(&Xs[r][0][0]),  sparse + (size_t)b * NF * DD,
                        SP_BYTES, mbar);
                bulk_ld(smem_u32(&Xs[r][26][0]), dense + (size_t)b * DD,
                        DN_BYTES, mbar);
            }
        }
    }

    // ---- overlap with DMA: zero pad row 27 + dense passthrough ----
    #pragma unroll
    for (int r = 0; r < RPW; r++) {
        reinterpret_cast<float4*>(&Xs[r][27][0])[lane] = make_float4(0.f, 0.f, 0.f, 0.f);
    }
    #pragma unroll
    for (int r = 0; r < RPW; r++) {
        const int b = b0 + r;
        if (b >= B_TOT) break;
        float4 dv = reinterpret_cast<const float4*>(dense + (size_t)b * DD)[lane];
        float* ob = out + (size_t)b * OUT_STRIDE;
        ob[4 * lane + 0] = dv.x;
        ob[4 * lane + 1] = dv.y;
        ob[4 * lane + 2] = dv.z;
        ob[4 * lane + 3] = dv.w;
    }

    // ---- wait for DMA completion (parity 0) ----
    {
        uint32_t done;
        asm volatile(
            "{\n\t.reg .pred p;\n\t"
            "mbarrier.try_wait.parity.acquire.cta.shared::cta.b64 p, [%1], %2;\n\t"
            "selp.b32 %0, 1, 0, p;\n\t}"
            : "=r"(done) : "r"(mbar), "r"(0u) : "memory");
        if (!done) {
            asm volatile(
                "{\n\t.reg .pred P1;\n\t"
                "WL_%=:\n\t"
                "mbarrier.try_wait.parity.acquire.cta.shared::cta.b64 P1, [%0], %1, 0x989680;\n\t"
                "@P1 bra.uni WD_%=;\n\t"
                "bra.uni WL_%=;\n\t"
                "WD_%=:\n\t}"
                :: "r"(mbar), "r"(0u) : "memory");
        }
    }
    __syncwarp();

    // ---- lane -> (row, tile): 3 rows x 10 upper-tri 7x7 tiles ----
    const int r  = lane / 10;                  // 0..2 (lanes 30,31 idle)
    const int t  = lane - r * 10;              // 0..9
    const int bc = b0 + r;
    const bool active = (lane < 30) && (bc < B_TOT);

    const int ti = (t < 4) ? 0 : (t < 7) ? 1 : (t < 9) ? 2 : 3;
    const int tj = (t < 4) ? t : (t < 7) ? t - 3 : (t < 9) ? t - 5 : 3;

    if (active) {
        unsigned long long acc2[7][7];         // packed f32x2 partial sums
        #pragma unroll
        for (int ii = 0; ii < 7; ii++)
            #pragma unroll
            for (int jj = 0; jj < 7; jj++)
                acc2[ii][jj] = 0ULL;

        const ulonglong2* __restrict__ pi2 =
            reinterpret_cast<const ulonglong2*>(&Xs[r][7 * ti][0]);
        const ulonglong2* __restrict__ pj2 =
            reinterpret_cast<const ulonglong2*>(&Xs[r][7 * tj][0]);

        // conflict-free: bank-quad = (kk+lane)&7, distinct within each
        // 8-lane phase group (row stride 128 floats = bank-aligned).
        #pragma unroll 4
        for (int kk = 0; kk < NQ; kk++) {
            const int kq = (kk + lane) & (NQ - 1);
            ulonglong2 xi[7], xj[7];
            #pragma unroll
            for (int ii = 0; ii < 7; ii++) xi[ii] = pi2[ii * NQ + kq];
            #pragma unroll
            for (int jj = 0; jj < 7; jj++) xj[jj] = pj2[jj * NQ + kq];
            #pragma unroll
            for (int ii = 0; ii < 7; ii++)
                #pragma unroll
                for (int jj = 0; jj < 7; jj++) {
                    ffma2(acc2[ii][jj], xi[ii].x, xj[jj].x);
                    ffma2(acc2[ii][jj], xi[ii].y, xj[jj].y);
                }
        }

        // ---- epilogue: horizontal add + scatter (i<j, j<=26) ----
        float* ob = out + (size_t)bc * OUT_STRIDE;
        #pragma unroll
        for (int ii = 0; ii < 7; ii++) {
            #pragma unroll
            for (int jj = 0; jj < 7; jj++) {
                const int i = 7 * ti + ii;
                const int j = 7 * tj + jj;
                if (i < j && j <= 26) {
                    float2 p = *reinterpret_cast<float2*>(&acc2[ii][jj]);
                    float v = p.x + p.y;
                    int dst;
                    if (j == 26) {
                        dst = 128 + i;                                        // sparse·dense
                    } else {
                        dst = 154 + i * 25 - (i * (i - 1)) / 2 + (j - i - 1); // pair
                    }
                    ob[dst] = v;
                }
            }
        }
    }
}

extern "C" void kernel_launch(void* const* d_in, const int* in_sizes, int n_in,
                              void* d_out, int out_size)
{
    (void)n_in; (void)out_size;
    const float* a = (const float*)d_in[0];
    const float* b = (const float*)d_in[1];
    // dense has B*D = 2,097,152 elems; sparse has B*F*D = 54,525,952 elems.
    const float* dense  = (in_sizes[0] < in_sizes[1]) ? a : b;
    const float* sparse = (in_sizes[0] < in_sizes[1]) ? b : a;

    const int grid = (B_TOT + RPW - 1) / RPW;
    interact_kernel<<<grid, 32>>>(dense, sparse, (float*)d_out);
}